// round 11
// baseline (speedup 1.0000x reference)
#include <cuda_runtime.h>
#include <math.h>

// Triplet-margin ranking loss, GB300 sm_103a — FINAL kernel (champion config,
// best measured 143.9us; LTS-cap floor ~139us for the 960MB stream).
//
// Structure: two kernels, static warp-per-row grid-stride, full occupancy.
// Measured landscape over 10 rounds:
//   - fusion of dap into the stream kernel: slower (R3 +9us, R4 +11us, R6 +19us)
//   - dynamic atomic-ticket scheduling: 2x slower (R2; single-address atomic
//     serializes at the L2 atomic ALU)
//   - reduced-occupancy balanced grid (625 blocks): slower (R8; 64 warps/SM is
//     the bandwidth lever at regs=32)
//   - issue-pressure micro-ops: neutral (R10; kernel is purely LTS-bound)
//
// anchor: (1, 2400) f32, positive: (P=5, 2400) f32, negative: (100000, 2400) f32
// loss = sum_{i<num_full} relu(d_ap[i % P] - d_an[i] + MARGIN)
// d_x = || anchor - x + EPS ||_2  (elementwise +EPS, torch pairwise_distance)

#define EPS    1e-6f
#define MARGIN 1.0f
#define DIM    2400
#define DIM4   (DIM / 4)   // 600 float4 per row

// d_ap values (P <= 8 supported; problem has P = 5)
__device__ float g_dap[8];

// ---------------------------------------------------------------------------
// Kernel 1: block b computes d_ap[b] (one positive row per block, 256 thr).
// Block 0 thread 0 also zeroes the poisoned output scalar.
// ---------------------------------------------------------------------------
__global__ void __launch_bounds__(256)
dap_kernel(const float* __restrict__ anchor,
           const float* __restrict__ pos,
           float* __restrict__ out,
           int P)
{
    __shared__ float sred[8];
    const int b    = blockIdx.x;
    const int wid  = threadIdx.x >> 5;
    const int lane = threadIdx.x & 31;

    if (b == 0 && threadIdx.x == 0) out[0] = 0.0f;
    if (b >= P) return;

    const float4* a4 = reinterpret_cast<const float4*>(anchor);
    const float4* p4 = reinterpret_cast<const float4*>(pos + (size_t)b * DIM);
    float s = 0.0f;
    for (int k = threadIdx.x; k < DIM4; k += blockDim.x) {
        float4 a = a4[k];
        float4 p = p4[k];
        float d0 = a.x - p.x + EPS;
        float d1 = a.y - p.y + EPS;
        float d2 = a.z - p.z + EPS;
        float d3 = a.w - p.w + EPS;
        s = fmaf(d0, d0, s);
        s = fmaf(d1, d1, s);
        s = fmaf(d2, d2, s);
        s = fmaf(d3, d3, s);
    }
    #pragma unroll
    for (int o = 16; o > 0; o >>= 1)
        s += __shfl_xor_sync(0xFFFFFFFFu, s, o);
    if (lane == 0) sred[wid] = s;
    __syncthreads();
    if (threadIdx.x == 0) {
        float t = 0.0f;
        #pragma unroll
        for (int i = 0; i < 8; i++) t += sred[i];
        g_dap[b] = sqrtf(t);
    }
}

// ---------------------------------------------------------------------------
// Kernel 2: streaming over negative rows. Warp-per-row, grid-stride, STATIC.
// Full occupancy (1184 blocks x 256 = 64 warps/SM, regs=32 = exact RF cap).
// Anchor staged in shared; negatives via __ldcs (evict-first, zero reuse).
// ---------------------------------------------------------------------------
__global__ void __launch_bounds__(256, 8)
loss_kernel(const float* __restrict__ anchor,
            const float* __restrict__ neg,
            float* __restrict__ out,
            int num_full, int P)
{
    __shared__ float4 sA[DIM4];        // anchor, 9600 B
    __shared__ float  sDap[8];
    __shared__ float  sWarp[8];

    // stage anchor into shared
    const float4* a4 = reinterpret_cast<const float4*>(anchor);
    for (int k = threadIdx.x; k < DIM4; k += blockDim.x)
        sA[k] = a4[k];
    if (threadIdx.x < 8)
        sDap[threadIdx.x] = (threadIdx.x < P) ? g_dap[threadIdx.x] : 0.0f;
    __syncthreads();

    const int wid    = threadIdx.x >> 5;
    const int lane   = threadIdx.x & 31;
    const int nwarps = blockDim.x >> 5;
    const int gwarp  = blockIdx.x * nwarps + wid;
    const int W      = gridDim.x * nwarps;

    float acc = 0.0f;

    for (int row = gwarp; row < num_full; row += W) {
        const float4* n4 = reinterpret_cast<const float4*>(neg + (size_t)row * DIM);
        float s = 0.0f;
        // 600 float4 / 32 lanes = 18.75 iterations; unroll 4 for MLP
        #pragma unroll 4
        for (int k = lane; k < DIM4; k += 32) {
            float4 a = sA[k];
            float4 n = __ldcs(&n4[k]);   // streaming: evict-first, no reuse
            float d0 = a.x - n.x + EPS;
            float d1 = a.y - n.y + EPS;
            float d2 = a.z - n.z + EPS;
            float d3 = a.w - n.w + EPS;
            s = fmaf(d0, d0, s);
            s = fmaf(d1, d1, s);
            s = fmaf(d2, d2, s);
            s = fmaf(d3, d3, s);
        }
        #pragma unroll
        for (int o = 16; o > 0; o >>= 1)
            s += __shfl_xor_sync(0xFFFFFFFFu, s, o);
        if (lane == 0) {
            float d_an = sqrtf(s);
            float t = sDap[row % P] - d_an + MARGIN;
            acc += (t > 0.0f) ? t : 0.0f;
        }
    }

    // block reduction: lane 0 of each warp holds its partial
    if (lane == 0) sWarp[wid] = acc;
    __syncthreads();
    if (threadIdx.x == 0) {
        float b = 0.0f;
        for (int i = 0; i < nwarps; i++) b += sWarp[i];
        atomicAdd(out, b);
    }
}

// ---------------------------------------------------------------------------
extern "C" void kernel_launch(void* const* d_in, const int* in_sizes, int n_in,
                              void* d_out, int out_size)
{
    const float* anchor = (const float*)d_in[0];
    const float* pos    = (const float*)d_in[1];
    const float* neg    = (const float*)d_in[2];
    float* out = (float*)d_out;

    const int P = in_sizes[1] / DIM;          // 5
    const int N = in_sizes[2] / DIM;          // 100000
    const int num_full = (N / P) * P;         // 100000

    dap_kernel<<<(P > 0 ? P : 1), 256>>>(anchor, pos, out, P);

    // 1184 blocks of 256 threads: full occupancy, the measured-fastest shape
    const int grid = 148 * 8;
    loss_kernel<<<grid, 256>>>(anchor, neg, out, num_full, P);
}

// round 12
// speedup vs baseline: 1.0145x; 1.0145x over previous
#include <cuda_runtime.h>
#include <math.h>

// Triplet-margin ranking loss, GB300 sm_103a — FINAL kernel (champion config;
// best measured 143.9us, re-validated 146.0us; noise band 141-146us against
// an LTS-cap floor of ~139us for the irreducible 960MB stream).
//
// Structure: two kernels, static warp-per-row grid-stride, full occupancy.
// Measured landscape over 11 rounds:
//   - fusion of dap into the stream kernel: slower (R3 +9us, R4 +11us, R6 +19us)
//   - dynamic atomic-ticket scheduling: 2x slower (R2; single-address atomics
//     serialize at the L2 atomic ALU)
//   - reduced-occupancy balanced grid (625 blocks): slower (R8; 64 warps/SM at
//     regs=32 is the bandwidth lever)
//   - issue-pressure micro-ops (EPS pre-add): pipe deltas as predicted, dur
//     unchanged (R10; kernel is purely memory-path-bound)
//   - TMA: non-avenue (LTS cap is path-independent on B300)
//
// anchor: (1, 2400) f32, positive: (P=5, 2400) f32, negative: (100000, 2400) f32
// loss = sum_{i<num_full} relu(d_ap[i % P] - d_an[i] + MARGIN)
// d_x = || anchor - x + EPS ||_2  (elementwise +EPS, torch pairwise_distance)

#define EPS    1e-6f
#define MARGIN 1.0f
#define DIM    2400
#define DIM4   (DIM / 4)   // 600 float4 per row

// d_ap values (P <= 8 supported; problem has P = 5)
__device__ float g_dap[8];

// ---------------------------------------------------------------------------
// Kernel 1: block b computes d_ap[b] (one positive row per block, 256 thr).
// Block 0 thread 0 also zeroes the poisoned output scalar.
// ---------------------------------------------------------------------------
__global__ void __launch_bounds__(256)
dap_kernel(const float* __restrict__ anchor,
           const float* __restrict__ pos,
           float* __restrict__ out,
           int P)
{
    __shared__ float sred[8];
    const int b    = blockIdx.x;
    const int wid  = threadIdx.x >> 5;
    const int lane = threadIdx.x & 31;

    if (b == 0 && threadIdx.x == 0) out[0] = 0.0f;
    if (b >= P) return;

    const float4* a4 = reinterpret_cast<const float4*>(anchor);
    const float4* p4 = reinterpret_cast<const float4*>(pos + (size_t)b * DIM);
    float s = 0.0f;
    for (int k = threadIdx.x; k < DIM4; k += blockDim.x) {
        float4 a = a4[k];
        float4 p = p4[k];
        float d0 = a.x - p.x + EPS;
        float d1 = a.y - p.y + EPS;
        float d2 = a.z - p.z + EPS;
        float d3 = a.w - p.w + EPS;
        s = fmaf(d0, d0, s);
        s = fmaf(d1, d1, s);
        s = fmaf(d2, d2, s);
        s = fmaf(d3, d3, s);
    }
    #pragma unroll
    for (int o = 16; o > 0; o >>= 1)
        s += __shfl_xor_sync(0xFFFFFFFFu, s, o);
    if (lane == 0) sred[wid] = s;
    __syncthreads();
    if (threadIdx.x == 0) {
        float t = 0.0f;
        #pragma unroll
        for (int i = 0; i < 8; i++) t += sred[i];
        g_dap[b] = sqrtf(t);
    }
}

// ---------------------------------------------------------------------------
// Kernel 2: streaming over negative rows. Warp-per-row, grid-stride, STATIC.
// Full occupancy (1184 blocks x 256 = 64 warps/SM, regs=32 = exact RF cap).
// Anchor staged in shared; negatives via __ldcs (evict-first, zero reuse).
// ---------------------------------------------------------------------------
__global__ void __launch_bounds__(256, 8)
loss_kernel(const float* __restrict__ anchor,
            const float* __restrict__ neg,
            float* __restrict__ out,
            int num_full, int P)
{
    __shared__ float4 sA[DIM4];        // anchor, 9600 B
    __shared__ float  sDap[8];
    __shared__ float  sWarp[8];

    // stage anchor into shared
    const float4* a4 = reinterpret_cast<const float4*>(anchor);
    for (int k = threadIdx.x; k < DIM4; k += blockDim.x)
        sA[k] = a4[k];
    if (threadIdx.x < 8)
        sDap[threadIdx.x] = (threadIdx.x < P) ? g_dap[threadIdx.x] : 0.0f;
    __syncthreads();

    const int wid    = threadIdx.x >> 5;
    const int lane   = threadIdx.x & 31;
    const int nwarps = blockDim.x >> 5;
    const int gwarp  = blockIdx.x * nwarps + wid;
    const int W      = gridDim.x * nwarps;

    float acc = 0.0f;

    for (int row = gwarp; row < num_full; row += W) {
        const float4* n4 = reinterpret_cast<const float4*>(neg + (size_t)row * DIM);
        float s = 0.0f;
        // 600 float4 / 32 lanes = 18.75 iterations; unroll 4 for MLP
        #pragma unroll 4
        for (int k = lane; k < DIM4; k += 32) {
            float4 a = sA[k];
            float4 n = __ldcs(&n4[k]);   // streaming: evict-first, no reuse
            float d0 = a.x - n.x + EPS;
            float d1 = a.y - n.y + EPS;
            float d2 = a.z - n.z + EPS;
            float d3 = a.w - n.w + EPS;
            s = fmaf(d0, d0, s);
            s = fmaf(d1, d1, s);
            s = fmaf(d2, d2, s);
            s = fmaf(d3, d3, s);
        }
        #pragma unroll
        for (int o = 16; o > 0; o >>= 1)
            s += __shfl_xor_sync(0xFFFFFFFFu, s, o);
        if (lane == 0) {
            float d_an = sqrtf(s);
            float t = sDap[row % P] - d_an + MARGIN;
            acc += (t > 0.0f) ? t : 0.0f;
        }
    }

    // block reduction: lane 0 of each warp holds its partial
    if (lane == 0) sWarp[wid] = acc;
    __syncthreads();
    if (threadIdx.x == 0) {
        float b = 0.0f;
        for (int i = 0; i < nwarps; i++) b += sWarp[i];
        atomicAdd(out, b);
    }
}

// ---------------------------------------------------------------------------
extern "C" void kernel_launch(void* const* d_in, const int* in_sizes, int n_in,
                              void* d_out, int out_size)
{
    const float* anchor = (const float*)d_in[0];
    const float* pos    = (const float*)d_in[1];
    const float* neg    = (const float*)d_in[2];
    float* out = (float*)d_out;

    const int P = in_sizes[1] / DIM;          // 5
    const int N = in_sizes[2] / DIM;          // 100000
    const int num_full = (N / P) * P;         // 100000

    dap_kernel<<<(P > 0 ? P : 1), 256>>>(anchor, pos, out, P);

    // 1184 blocks of 256 threads: full occupancy, the measured-fastest shape
    const int grid = 148 * 8;
    loss_kernel<<<grid, 256>>>(anchor, neg, out, num_full, P);
}